// round 14
// baseline (speedup 1.0000x reference)
#include <cuda_runtime.h>
#include <cuda_fp16.h>
#include <cstdint>

#define D     128
#define NSEG  4096
#define BM    256
#define NTHR  512
#define CH    1024
#define RSEG  32
#define NMAX  1000000

#define WS    136            // padded fp16 row stride (272B)
#define WS2   (WS * 2)
#define XTILE (BM * WS2)     // 69632 B
#define WTILE (D * WS2)      // 34816 B

// smem byte offsets
#define OX0  0
#define OX1  (XTILE)
#define OW1  (2 * XTILE)
#define OW2  (2 * XTILE + WTILE)
#define OB1  (2 * XTILE + 2 * WTILE)
#define OB2  (OB1 + 512)
#define OIDX0 (OB2 + 512)
#define OIDX1 (OIDX0 + 1024)
#define SMEM_PHI (OIDX1 + 1024)     // ~207 KB

// ---------------- scratch ----------------------------------------------------
__device__ float  g_xsum[NSEG * D];
__device__ float  g_rho [NSEG * D];
__device__ __half g_xh  [(size_t)NMAX * D];   // fp16 copy of x (built by segsum)

// ---------------- helpers ----------------------------------------------------
__device__ __forceinline__ uint32_t smem_u32(const void* p) {
    uint32_t a;
    asm("{ .reg .u64 t; cvta.to.shared.u64 t, %1; cvt.u32.u64 %0, t; }"
        : "=r"(a) : "l"(p));
    return a;
}
__device__ __forceinline__ void ldsm_x4(uint32_t r[4], uint32_t addr) {
    asm volatile("ldmatrix.sync.aligned.m8n8.x4.shared.b16 {%0,%1,%2,%3}, [%4];"
                 : "=r"(r[0]), "=r"(r[1]), "=r"(r[2]), "=r"(r[3]) : "r"(addr));
}
__device__ __forceinline__ void mma_f16(float c[4], const uint32_t a[4],
                                        const uint32_t* b) {
    asm volatile("mma.sync.aligned.m16n8k16.row.col.f32.f16.f16.f32 "
                 "{%0,%1,%2,%3}, {%4,%5,%6,%7}, {%8,%9}, {%0,%1,%2,%3};"
                 : "+f"(c[0]), "+f"(c[1]), "+f"(c[2]), "+f"(c[3])
                 : "r"(a[0]), "r"(a[1]), "r"(a[2]), "r"(a[3]),
                   "r"(b[0]), "r"(b[1]));
}
__device__ __forceinline__ uint32_t packh2(float a, float b) {
    __half2 h = __floats2half2_rn(a, b);
    return *(uint32_t*)&h;
}
__device__ __forceinline__ void cp16(uint32_t dst, const void* src) {
    asm volatile("cp.async.cg.shared.global [%0], [%1], 16;"
                 :: "r"(dst), "l"(src) : "memory");
}
#define CP_COMMIT() asm volatile("cp.async.commit_group;" ::: "memory")
#define CP_WAIT0()  asm volatile("cp.async.wait_group 0;" ::: "memory")

// ---------------- k0: zero ---------------------------------------------------
__global__ void k_zero() {
    int i = blockIdx.x * blockDim.x + threadIdx.x;
    if (i < NSEG * D / 4)
        reinterpret_cast<float4*>(g_xsum)[i] = make_float4(0.f, 0.f, 0.f, 0.f);
}

// ---------------- k1: segment sum + fused fp16 conversion (octet lanes) --------
__global__ void k_segsum(const float4* __restrict__ x4,
                         const int*    __restrict__ idx, int n) {
    int oct = threadIdx.x & 15;       // 8-float chunk 0..15
    int rg  = threadIdx.x >> 4;       // row group 0..15
    long start = (long)blockIdx.x * CH;
    long end = start + CH; if (end > n) end = n;
    long nn = start + rg;
    if (nn >= end) return;

    int    cur = __ldg(&idx[nn]);
    float4 a0 = make_float4(0.f, 0.f, 0.f, 0.f);
    float4 a1 = make_float4(0.f, 0.f, 0.f, 0.f);

    auto flush = [&](int seg) {
        float* dst = &g_xsum[(long)seg * D + oct * 8];
        atomicAdd(dst,     a0.x); atomicAdd(dst + 1, a0.y);
        atomicAdd(dst + 2, a0.z); atomicAdd(dst + 3, a0.w);
        atomicAdd(dst + 4, a1.x); atomicAdd(dst + 5, a1.y);
        atomicAdd(dst + 6, a1.z); atomicAdd(dst + 7, a1.w);
        a0 = make_float4(0.f, 0.f, 0.f, 0.f);
        a1 = make_float4(0.f, 0.f, 0.f, 0.f);
    };
    auto step = [&](long row, int s, const float4& v0, const float4& v1) {
        uint32_t h0 = packh2(v0.x, v0.y), h1 = packh2(v0.z, v0.w);
        uint32_t h2 = packh2(v1.x, v1.y), h3 = packh2(v1.z, v1.w);
        asm volatile("st.global.cs.v4.b32 [%0], {%1,%2,%3,%4};"
            :: "l"(&g_xh[row * D + oct * 8]),
               "r"(h0), "r"(h1), "r"(h2), "r"(h3) : "memory");
        if (s != cur) { flush(cur); cur = s; }
        a0.x += v0.x; a0.y += v0.y; a0.z += v0.z; a0.w += v0.w;
        a1.x += v1.x; a1.y += v1.y; a1.z += v1.z; a1.w += v1.w;
    };

    for (; nn + 48 < end; nn += 64) {       // 4 steps of stride-16
        int s[4]; float4 v0[4], v1[4];
        #pragma unroll
        for (int u = 0; u < 4; u++) {
            long row = nn + u * 16;
            s[u]  = __ldg(&idx[row]);
            v0[u] = __ldcs(&x4[row * 32 + oct * 2]);
            v1[u] = __ldcs(&x4[row * 32 + oct * 2 + 1]);
        }
        #pragma unroll
        for (int u = 0; u < 4; u++) step(nn + u * 16, s[u], v0[u], v1[u]);
    }
    for (; nn < end; nn += 16) {
        int s = __ldg(&idx[nn]);
        float4 v0 = __ldcs(&x4[nn * 32 + oct * 2]);
        float4 v1 = __ldcs(&x4[nn * 32 + oct * 2 + 1]);
        step(nn, s, v0, v1);
    }
    flush(cur);
}

// ---------------- k2: rho MLP on segment sums (256 thr) -------------------------
__global__ void k_rho(const float* __restrict__ w1, const float* __restrict__ b1,
                      const float* __restrict__ w2, const float* __restrict__ b2) {
    extern __shared__ float sm[];
    float* sW = sm;                    // D*D
    float* sX = sW + D * D;            // RSEG*D
    float* sH = sX + RSEG * D;         // RSEG*D
    float* sB = sH + RSEG * D;         // D
    int tid = threadIdx.x;             // 256 threads
    int j = tid & 127;
    int rh = tid >> 7;                 // 0/1: row half
    int seg0 = blockIdx.x * RSEG;

    for (int r = rh; r < RSEG; r += 2)
        sX[r * D + j] = g_xsum[(seg0 + r) * D + j];
    for (int i = tid; i < D * D; i += 256) sW[i] = w1[i];
    if (tid < D) sB[tid] = b1[tid];
    __syncthreads();

    for (int r = rh; r < RSEG; r += 2) {
        float acc = sB[j];
        #pragma unroll 8
        for (int k = 0; k < D; k++) acc += sX[r * D + k] * sW[k * D + j];
        sH[r * D + j] = fmaxf(acc, 0.f);
    }
    __syncthreads();
    for (int i = tid; i < D * D; i += 256) sW[i] = w2[i];
    if (tid < D) sB[tid] = b2[tid];
    __syncthreads();

    for (int r = rh; r < RSEG; r += 2) {
        float acc = sB[j];
        #pragma unroll 8
        for (int k = 0; k < D; k++) acc += sH[r * D + k] * sW[k * D + j];
        g_rho[(seg0 + r) * D + j] = acc;
    }
}

// ---------------- fp16 GEMM, warp tile 64x32 ------------------------------------
__device__ __forceinline__ void mma_layer(uint32_t sb, uint32_t aOff, uint32_t bOff,
                                          uint32_t aRow, uint32_t bRow,
                                          float acc[4][4][4]) {
    #pragma unroll
    for (int k = 0; k < 8; k++) {
        uint32_t a[4][4];
        #pragma unroll
        for (int mt = 0; mt < 4; mt++)
            ldsm_x4(a[mt], sb + aOff + aRow + mt * 16 * WS2 + k * 32);
        #pragma unroll
        for (int np = 0; np < 2; np++) {
            uint32_t b[4];
            ldsm_x4(b, sb + bOff + bRow + np * 16 * WS2 + k * 32);
            #pragma unroll
            for (int mt = 0; mt < 4; mt++) {
                mma_f16(acc[mt][2*np],   a[mt], b);
                mma_f16(acc[mt][2*np+1], a[mt], b + 2);
            }
        }
    }
}

// ---------------- k3: phi MLP (fp16 from g_xh, BM=256, double-buffered) ---------
__global__ __launch_bounds__(NTHR, 1)
void k_phi(const int* __restrict__ idx,
           const float* __restrict__ w1, const float* __restrict__ b1,
           const float* __restrict__ w2, const float* __restrict__ b2,
           float* __restrict__ out, int n) {
    extern __shared__ char smem[];
    const uint32_t sb = smem_u32(smem);
    int tid = threadIdx.x, wid = tid >> 5, lane = tid & 31;
    int wm = wid >> 2, wn = wid & 3;      // 4 x 4 warp grid, warp tile 64x32

    // ---- prologue: weights -> W^T fp16, biases ----
    for (int i = tid; i < D * D; i += NTHR) {      // i = k*128 + j
        int k = i >> 7, j = i & 127;
        uint32_t o = (uint32_t)(j * WS + k) * 2;
        *(__half*)(smem + OW1 + o) = __float2half_rn(w1[i]);
        *(__half*)(smem + OW2 + o) = __float2half_rn(w2[i]);
    }
    if (tid < D) {
        ((float*)(smem + OB1))[tid] = b1[tid];
        ((float*)(smem + OB2))[tid] = b2[tid];
    }

    const float* sB1 = (const float*)(smem + OB1);
    const float* sB2 = (const float*)(smem + OB2);

    const uint32_t aRow = (uint32_t)(wm * 64 + (lane & 15)) * WS2
                        + (uint32_t)((lane >> 4) << 4);
    const uint32_t bRow = (uint32_t)(wn * 32 + (lane & 7) + ((lane >> 4) << 3)) * WS2
                        + (uint32_t)(((lane >> 3) & 1) << 4);

    const int ntiles = (n + BM - 1) / BM;

    // prefetch fp16 x rows + idx of tile t into OX{buf}/OIDX{buf}
    auto prefetch = [&](int t, int buf) {
        long pb = (long)t * BM;
        uint32_t ox = buf ? (uint32_t)OX1 : (uint32_t)OX0;
        #pragma unroll
        for (int it = 0; it < 8; ++it) {
            int c = it * NTHR + tid;          // chunk 0..4095 (16B each)
            int m = c >> 4, q = c & 15;
            if (pb + m < n)
                cp16(sb + ox + (uint32_t)(m * WS2 + q * 16),
                     (const char*)g_xh + ((pb + m) * D + q * 8) * 2);
        }
        uint32_t oidx = buf ? (uint32_t)OIDX1 : (uint32_t)OIDX0;
        if (tid < 64 && pb + tid * 4 < n)     // 256 ints = 64 chunks
            cp16(sb + oidx + tid * 16, idx + pb + tid * 4);
        CP_COMMIT();
    };

    int tile = blockIdx.x;
    int cnt = 0;
    if (tile < ntiles) prefetch(tile, 0);

    for (; tile < ntiles; tile += gridDim.x, cnt ^= 1) {
        long base = (long)tile * BM;
        uint32_t ox = cnt ? (uint32_t)OX1 : (uint32_t)OX0;
        const int* sIdx = (const int*)(smem + (cnt ? OIDX1 : OIDX0));

        CP_WAIT0();
        __syncthreads();   // current buffers ready; previous tile consumed

        // ---- issue prefetch for next tile into the other buffers ----
        int nxt = tile + gridDim.x;
        if (nxt < ntiles) prefetch(nxt, cnt ^ 1);

        // ---- layer 1 ----
        float acc[4][4][4];
        #pragma unroll
        for (int a = 0; a < 4; a++)
            #pragma unroll
            for (int b = 0; b < 4; b++)
                #pragma unroll
                for (int c = 0; c < 4; c++) acc[a][b][c] = 0.f;
        mma_layer(sb, ox, OW1, aRow, bRow, acc);
        __syncthreads();   // warps sharing rows done reading X

        // ---- epilogue 1: relu(.+b1) -> fp16 H back into same buffer ----
        #pragma unroll
        for (int mt = 0; mt < 4; mt++) {
            int r0 = wm * 64 + mt * 16 + (lane >> 2);
            #pragma unroll
            for (int nt = 0; nt < 4; nt++) {
                int col = wn * 32 + nt * 8 + (lane & 3) * 2;
                float* c = acc[mt][nt];
                float v0 = fmaxf(c[0] + sB1[col],     0.f);
                float v1 = fmaxf(c[1] + sB1[col + 1], 0.f);
                float v2 = fmaxf(c[2] + sB1[col],     0.f);
                float v3 = fmaxf(c[3] + sB1[col + 1], 0.f);
                *(uint32_t*)(smem + ox + (uint32_t)(r0 * WS + col) * 2)
                    = packh2(v0, v1);
                *(uint32_t*)(smem + ox + (uint32_t)((r0 + 8) * WS + col) * 2)
                    = packh2(v2, v3);
            }
        }
        __syncthreads();

        // ---- layer 2 ----
        #pragma unroll
        for (int a = 0; a < 4; a++)
            #pragma unroll
            for (int b = 0; b < 4; b++)
                #pragma unroll
                for (int c = 0; c < 4; c++) acc[a][b][c] = 0.f;
        mma_layer(sb, ox, OW2, aRow, bRow, acc);

        // ---- writeout: + b2 + rho[idx], streaming stores ----
        #pragma unroll
        for (int mt = 0; mt < 4; mt++) {
            int rl = wm * 64 + mt * 16 + (lane >> 2);
            #pragma unroll
            for (int half = 0; half < 2; half++) {
                int row = rl + half * 8;
                long grow = base + row;
                if (grow < n) {
                    int seg = sIdx[row];
                    const float* rrow = &g_rho[(long)seg * D];
                    float* orow = &out[grow * D];
                    #pragma unroll
                    for (int nt = 0; nt < 4; nt++) {
                        int col = wn * 32 + nt * 8 + (lane & 3) * 2;
                        float* c = acc[mt][nt];
                        float2 g = *(const float2*)&rrow[col];
                        float2 o;
                        o.x = c[2 * half]     + sB2[col]     + g.x;
                        o.y = c[2 * half + 1] + sB2[col + 1] + g.y;
                        __stcs((float2*)&orow[col], o);
                    }
                }
            }
        }
    }
}

// ---------------- launch --------------------------------------------------------
extern "C" void kernel_launch(void* const* d_in, const int* in_sizes, int n_in,
                              void* d_out, int out_size) {
    const float* x      = (const float*)d_in[0];
    const int*   idx    = (const int*)  d_in[1];
    const float* phi_w1 = (const float*)d_in[2];
    const float* phi_b1 = (const float*)d_in[3];
    const float* phi_w2 = (const float*)d_in[4];
    const float* phi_b2 = (const float*)d_in[5];
    const float* rho_w1 = (const float*)d_in[6];
    const float* rho_b1 = (const float*)d_in[7];
    const float* rho_w2 = (const float*)d_in[8];
    const float* rho_b2 = (const float*)d_in[9];
    float* out = (float*)d_out;
    int n = in_sizes[1];

    size_t smem_rho = (size_t)(D * D + 2 * RSEG * D + D) * sizeof(float);
    cudaFuncSetAttribute(k_rho, cudaFuncAttributeMaxDynamicSharedMemorySize,
                         (int)smem_rho);
    cudaFuncSetAttribute(k_phi, cudaFuncAttributeMaxDynamicSharedMemorySize,
                         SMEM_PHI);

    k_zero<<<(NSEG * D / 4 + 255) / 256, 256>>>();

    int segsum_blocks = (n + CH - 1) / CH;
    k_segsum<<<segsum_blocks, 256>>>((const float4*)x, idx, n);

    k_rho<<<NSEG / RSEG, 256, smem_rho>>>(rho_w1, rho_b1, rho_w2, rho_b2);

    k_phi<<<152, NTHR, SMEM_PHI>>>(idx, phi_w1, phi_b1, phi_w2, phi_b2,
                                   out, n);
}

// round 15
// speedup vs baseline: 1.1367x; 1.1367x over previous
#include <cuda_runtime.h>
#include <cuda_fp16.h>
#include <cstdint>

#define D     128
#define NSEG  4096
#define BM    128
#define NTHR  512
#define CH    2048
#define RSEG  32

#define WS    136            // padded fp16 row stride (272B)
#define WS2   (WS * 2)
#define TILE  (BM * WS2)     // 34816 B

// smem byte offsets
#define OX    0
#define OH0   (TILE)
#define OH1   (2 * TILE)
#define OW1   (3 * TILE)
#define OW2   (4 * TILE)
#define OB1   (5 * TILE)
#define OB2   (5 * TILE + 512)
#define OIDX0 (5 * TILE + 1024)
#define OIDX1 (5 * TILE + 1536)
#define SMEM_PHI (5 * TILE + 2048)   // 176128 B

// named barriers: 1 = group-A internal (256); FULL(b)=4+b, EMPTY(b)=6+b (512)
#define BARA()       asm volatile("bar.sync 1, 256;" ::: "memory")
#define BSYNC(id)    asm volatile("bar.sync %0, 512;"   :: "r"(id) : "memory")
#define BARRIVE(id)  asm volatile("bar.arrive %0, 512;" :: "r"(id) : "memory")

// ---------------- scratch ----------------------------------------------------
__device__ float g_xsum[NSEG * D];
__device__ float g_rho [NSEG * D];

// ---------------- helpers ----------------------------------------------------
__device__ __forceinline__ uint32_t smem_u32(const void* p) {
    uint32_t a;
    asm("{ .reg .u64 t; cvta.to.shared.u64 t, %1; cvt.u32.u64 %0, t; }"
        : "=r"(a) : "l"(p));
    return a;
}
__device__ __forceinline__ void ldsm_x4(uint32_t r[4], uint32_t addr) {
    asm volatile("ldmatrix.sync.aligned.m8n8.x4.shared.b16 {%0,%1,%2,%3}, [%4];"
                 : "=r"(r[0]), "=r"(r[1]), "=r"(r[2]), "=r"(r[3]) : "r"(addr));
}
__device__ __forceinline__ void mma_f16(float c[4], const uint32_t a[4],
                                        const uint32_t* b) {
    asm volatile("mma.sync.aligned.m16n8k16.row.col.f32.f16.f16.f32 "
                 "{%0,%1,%2,%3}, {%4,%5,%6,%7}, {%8,%9}, {%0,%1,%2,%3};"
                 : "+f"(c[0]), "+f"(c[1]), "+f"(c[2]), "+f"(c[3])
                 : "r"(a[0]), "r"(a[1]), "r"(a[2]), "r"(a[3]),
                   "r"(b[0]), "r"(b[1]));
}
__device__ __forceinline__ uint32_t packh2(float a, float b) {
    __half2 h = __floats2half2_rn(a, b);
    return *(uint32_t*)&h;
}

// ---------------- k0: zero ---------------------------------------------------
__global__ void k_zero() {
    int i = blockIdx.x * blockDim.x + threadIdx.x;
    if (i < NSEG * D / 4)
        reinterpret_cast<float4*>(g_xsum)[i] = make_float4(0.f, 0.f, 0.f, 0.f);
}

// ---------------- k1: segment sum (R12 version) --------------------------------
__global__ void k_segsum(const float4* __restrict__ x4,
                         const int*    __restrict__ idx, int n) {
    int lane = threadIdx.x & 31;
    int rg   = threadIdx.x >> 5;      // 0..15
    long start = (long)blockIdx.x * CH;
    long end = start + CH; if (end > n) end = n;
    long nn = start + rg;
    if (nn >= end) return;

    int    cur = __ldg(&idx[nn]);
    float4 acc = make_float4(0.f, 0.f, 0.f, 0.f);

    for (; nn + 112 < end; nn += 128) {
        int s[8]; float4 v[8];
        #pragma unroll
        for (int u = 0; u < 8; u++) {
            s[u] = __ldg(&idx[nn + u * 16]);
            v[u] = __ldcs(&x4[(nn + u * 16) * 32 + lane]);
        }
        #pragma unroll
        for (int u = 0; u < 8; u++) {
            if (s[u] != cur) {
                float* dst = &g_xsum[(long)cur * D + lane * 4];
                atomicAdd(dst,     acc.x); atomicAdd(dst + 1, acc.y);
                atomicAdd(dst + 2, acc.z); atomicAdd(dst + 3, acc.w);
                acc = make_float4(0.f, 0.f, 0.f, 0.f); cur = s[u];
            }
            acc.x += v[u].x; acc.y += v[u].y; acc.z += v[u].z; acc.w += v[u].w;
        }
    }
    for (; nn < end; nn += 16) {
        int s = __ldg(&idx[nn]);
        float4 v = __ldcs(&x4[nn * 32 + lane]);
        if (s != cur) {
            float* dst = &g_xsum[(long)cur * D + lane * 4];
            atomicAdd(dst,     acc.x); atomicAdd(dst + 1, acc.y);
            atomicAdd(dst + 2, acc.z); atomicAdd(dst + 3, acc.w);
            acc = make_float4(0.f, 0.f, 0.f, 0.f); cur = s;
        }
        acc.x += v.x; acc.y += v.y; acc.z += v.z; acc.w += v.w;
    }
    float* dst = &g_xsum[(long)cur * D + lane * 4];
    atomicAdd(dst,     acc.x); atomicAdd(dst + 1, acc.y);
    atomicAdd(dst + 2, acc.z); atomicAdd(dst + 3, acc.w);
}

// ---------------- k2: rho MLP (R12 version) -------------------------------------
__global__ void k_rho(const float* __restrict__ w1, const float* __restrict__ b1,
                      const float* __restrict__ w2, const float* __restrict__ b2) {
    extern __shared__ float sm[];
    float* sW = sm;
    float* sX = sW + D * D;
    float* sH = sX + RSEG * D;
    float* sB = sH + RSEG * D;
    int tid = threadIdx.x;
    int j = tid & 127;
    int rh = tid >> 7;
    int seg0 = blockIdx.x * RSEG;

    for (int r = rh; r < RSEG; r += 2)
        sX[r * D + j] = g_xsum[(seg0 + r) * D + j];
    for (int i = tid; i < D * D; i += 256) sW[i] = w1[i];
    if (tid < D) sB[tid] = b1[tid];
    __syncthreads();

    for (int r = rh; r < RSEG; r += 2) {
        float acc = sB[j];
        #pragma unroll 8
        for (int k = 0; k < D; k++) acc += sX[r * D + k] * sW[k * D + j];
        sH[r * D + j] = fmaxf(acc, 0.f);
    }
    __syncthreads();
    for (int i = tid; i < D * D; i += 256) sW[i] = w2[i];
    if (tid < D) sB[tid] = b2[tid];
    __syncthreads();

    for (int r = rh; r < RSEG; r += 2) {
        float acc = sB[j];
        #pragma unroll 8
        for (int k = 0; k < D; k++) acc += sH[r * D + k] * sW[k * D + j];
        g_rho[(seg0 + r) * D + j] = acc;
    }
}

// ---------------- fp16 GEMM, warp tile 32x64 (8 warps cover 128x128) ------------
__device__ __forceinline__ void mma_layer(uint32_t sb, uint32_t aOff, uint32_t bOff,
                                          uint32_t aRow, uint32_t bRow,
                                          float acc[2][8][4]) {
    #pragma unroll
    for (int k = 0; k < 8; k++) {
        uint32_t a0[4], a1[4];
        ldsm_x4(a0, sb + aOff + aRow + k * 32);
        ldsm_x4(a1, sb + aOff + aRow + 16 * WS2 + k * 32);
        #pragma unroll
        for (int np = 0; np < 4; np++) {
            uint32_t b[4];
            ldsm_x4(b, sb + bOff + bRow + np * 16 * WS2 + k * 32);
            mma_f16(acc[0][2*np],   a0, b);
            mma_f16(acc[0][2*np+1], a0, b + 2);
            mma_f16(acc[1][2*np],   a1, b);
            mma_f16(acc[1][2*np+1], a1, b + 2);
        }
    }
}

// ---------------- k3: phi MLP, warp-specialized producer/consumer ---------------
__global__ __launch_bounds__(NTHR, 1)
void k_phi(const float* __restrict__ x, const int* __restrict__ idx,
           const float* __restrict__ w1, const float* __restrict__ b1,
           const float* __restrict__ w2, const float* __restrict__ b2,
           float* __restrict__ out, int n) {
    extern __shared__ char smem[];
    const uint32_t sb = smem_u32(smem);
    int tid = threadIdx.x, wid = tid >> 5, lane = tid & 31;

    // ---- prologue (all 512): weights -> W^T fp16, biases ----
    for (int i = tid; i < D * D; i += NTHR) {      // i = k*128 + j
        int k = i >> 7, j = i & 127;
        uint32_t o = (uint32_t)(j * WS + k) * 2;
        *(__half*)(smem + OW1 + o) = __float2half_rn(w1[i]);
        *(__half*)(smem + OW2 + o) = __float2half_rn(w2[i]);
    }
    if (tid < D) {
        ((float*)(smem + OB1))[tid] = b1[tid];
        ((float*)(smem + OB2))[tid] = b2[tid];
    }
    __syncthreads();   // last full-block barrier before specialization

    const float* sB1 = (const float*)(smem + OB1);
    const float* sB2 = (const float*)(smem + OB2);

    const int ntiles = (n + BM - 1) / BM;
    const bool isA = (tid < 256);
    int gw = wid & 7;                       // warp id within group (0..7)
    int wm = gw >> 1, wn = gw & 1;          // 4 x 2 grid, warp tile 32x64
    int gtid = tid & 255;

    const uint32_t aRow = (uint32_t)(wm * 32 + (lane & 15)) * WS2
                        + (uint32_t)((lane >> 4) << 4);
    const uint32_t bRow = (uint32_t)(wn * 64 + (lane & 7) + ((lane >> 4) << 3)) * WS2
                        + (uint32_t)(((lane >> 3) & 1) << 4);

    if (isA) {
        // ================= GROUP A: stage X, layer 1, produce H ==============
        const float4* xv = (const float4*)x;
        int c = 0;
        for (int tile = blockIdx.x; tile < ntiles; tile += gridDim.x, ++c) {
            int b = c & 1;
            uint32_t oh = b ? (uint32_t)OH1 : (uint32_t)OH0;
            int* sIdx = (int*)(smem + (b ? OIDX1 : OIDX0));

            if (c >= 2) BSYNC(6 + b);       // wait H[b]/idx[b] free

            long base = (long)tile * BM;
            // stage X -> fp16 smem (256 threads, 16 iters)
            #pragma unroll
            for (int it = 0; it < 16; ++it) {
                int i = it * 256 + gtid;    // 0..4095 float4 slots
                int m = i >> 5, kq = i & 31;
                float4 v = make_float4(0.f, 0.f, 0.f, 0.f);
                if (base + m < n) v = __ldcs(&xv[(base + m) * 32 + kq]);
                uint32_t o = (uint32_t)(m * WS + kq * 4) * 2;
                *(uint2*)(smem + OX + o) = make_uint2(packh2(v.x, v.y),
                                                      packh2(v.z, v.w));
            }
            if (gtid < BM) {
                int s = 0;
                if (base + gtid < n) s = __ldg(&idx[base + gtid]);
                sIdx[gtid] = s;
            }
            BARA();                         // X staged (group A only)

            // layer 1
            float acc[2][8][4];
            #pragma unroll
            for (int a = 0; a < 2; a++)
                #pragma unroll
                for (int b2_ = 0; b2_ < 8; b2_++)
                    #pragma unroll
                    for (int cc = 0; cc < 4; cc++) acc[a][b2_][cc] = 0.f;
            mma_layer(sb, OX, OW1, aRow, bRow, acc);

            // epilogue: relu(.+b1) -> H[b]
            #pragma unroll
            for (int mt = 0; mt < 2; mt++) {
                int r0 = wm * 32 + mt * 16 + (lane >> 2);
                #pragma unroll
                for (int nt = 0; nt < 8; nt++) {
                    int col = wn * 64 + nt * 8 + (lane & 3) * 2;
                    float* cch = acc[mt][nt];
                    float v0 = fmaxf(cch[0] + sB1[col],     0.f);
                    float v1 = fmaxf(cch[1] + sB1[col + 1], 0.f);
                    float v2 = fmaxf(cch[2] + sB1[col],     0.f);
                    float v3 = fmaxf(cch[3] + sB1[col + 1], 0.f);
                    *(uint32_t*)(smem + oh + (uint32_t)(r0 * WS + col) * 2)
                        = packh2(v0, v1);
                    *(uint32_t*)(smem + oh + (uint32_t)((r0 + 8) * WS + col) * 2)
                        = packh2(v2, v3);
                }
            }
            BARA();                         // all A: H written, X reads done
            BARRIVE(4 + b);                 // H[b] full -> group B
        }
    } else {
        // ================= GROUP B: layer 2 from H, writeout =================
        int c = 0;
        for (int tile = blockIdx.x; tile < ntiles; tile += gridDim.x, ++c) {
            int b = c & 1;
            uint32_t oh = b ? (uint32_t)OH1 : (uint32_t)OH0;
            const int* sIdx = (const int*)(smem + (b ? OIDX1 : OIDX0));

            BSYNC(4 + b);                   // wait H[b] full

            float acc[2][8][4];
            #pragma unroll
            for (int a = 0; a < 2; a++)
                #pragma unroll
                for (int b2_ = 0; b2_ < 8; b2_++)
                    #pragma unroll
                    for (int cc = 0; cc < 4; cc++) acc[a][b2_][cc] = 0.f;
            mma_layer(sb, oh, OW2, aRow, bRow, acc);

            long base = (long)tile * BM;
            #pragma unroll
            for (int mt = 0; mt < 2; mt++) {
                int rl = wm * 32 + mt * 16 + (lane >> 2);
                #pragma unroll
                for (int half = 0; half < 2; half++) {
                    int row = rl + half * 8;
                    long grow = base + row;
                    if (grow < n) {
                        int seg = sIdx[row];
                        const float* rrow = &g_rho[(long)seg * D];
                        float* orow = &out[grow * D];
                        #pragma unroll
                        for (int nt = 0; nt < 8; nt++) {
                            int col = wn * 64 + nt * 8 + (lane & 3) * 2;
                            float* cch = acc[mt][nt];
                            float2 g = *(const float2*)&rrow[col];
                            float2 o;
                            o.x = cch[2 * half]     + sB2[col]     + g.x;
                            o.y = cch[2 * half + 1] + sB2[col + 1] + g.y;
                            __stcs((float2*)&orow[col], o);
                        }
                    }
                }
            }
            BARRIVE(6 + b);                 // H[b]/idx[b] empty -> group A
        }
    }
}

// ---------------- launch --------------------------------------------------------
extern "C" void kernel_launch(void* const* d_in, const int* in_sizes, int n_in,
                              void* d_out, int out_size) {
    const float* x      = (const float*)d_in[0];
    const int*   idx    = (const int*)  d_in[1];
    const float* phi_w1 = (const float*)d_in[2];
    const float* phi_b1 = (const float*)d_in[3];
    const float* phi_w2 = (const float*)d_in[4];
    const float* phi_b2 = (const float*)d_in[5];
    const float* rho_w1 = (const float*)d_in[6];
    const float* rho_b1 = (const float*)d_in[7];
    const float* rho_w2 = (const float*)d_in[8];
    const float* rho_b2 = (const float*)d_in[9];
    float* out = (float*)d_out;
    int n = in_sizes[1];

    size_t smem_rho = (size_t)(D * D + 2 * RSEG * D + D) * sizeof(float);
    cudaFuncSetAttribute(k_rho, cudaFuncAttributeMaxDynamicSharedMemorySize,
                         (int)smem_rho);
    cudaFuncSetAttribute(k_phi, cudaFuncAttributeMaxDynamicSharedMemorySize,
                         SMEM_PHI);

    k_zero<<<(NSEG * D / 4 + 255) / 256, 256>>>();

    int segsum_blocks = (n + CH - 1) / CH;
    k_segsum<<<segsum_blocks, 512>>>((const float4*)x, idx, n);

    k_rho<<<NSEG / RSEG, 256, smem_rho>>>(rho_w1, rho_b1, rho_w2, rho_b2);

    k_phi<<<152, NTHR, SMEM_PHI>>>(x, idx, phi_w1, phi_b1, phi_w2, phi_b2,
                                   out, n);
}